// round 15
// baseline (speedup 1.0000x reference)
#include <cuda_runtime.h>
#include <math.h>

#define DOF 7
#define BATCH 16384
#define NTHREADS 64          // 2 warps per block, 32 elements/block
#define ACTION_RANGE 50.0f
#define MAX_VEL 20.0f
#define TSTEP 0.1f

typedef unsigned long long u64;

struct Params {
    float w[DOF][3];
    float v[DOF][3];
    float wxv[DOF][3];
    float wdv[DOF];
    float Rm[DOF][9];     // trans_inv(Mlist[i]) rotation
    float pm[DOF][3];     // trans_inv(Mlist[i]) translation
    float Gd[DOF][6];
    float Mr[DOF + 1][9]; // Mlist rotations (FK)
    float Mp[DOF + 1][3]; // Mlist translations (FK)
};

// ---------------- packed f32x2 helpers ----------------
__device__ __forceinline__ u64 pk2(float lo, float hi) {
    u64 r; asm("mov.b64 %0, {%1,%2};" : "=l"(r) : "f"(lo), "f"(hi)); return r;
}
__device__ __forceinline__ u64 pkb(float x) { return pk2(x, x); }
__device__ __forceinline__ void upk2(u64 v, float& lo, float& hi) {
    asm("mov.b64 {%0,%1}, %2;" : "=f"(lo), "=f"(hi) : "l"(v));
}
__device__ __forceinline__ u64 swap2(u64 v) {
    float lo, hi; upk2(v, lo, hi); return pk2(hi, lo);
}
__device__ __forceinline__ u64 f2mul(u64 a, u64 b) {
    u64 d; asm("mul.rn.f32x2 %0, %1, %2;" : "=l"(d) : "l"(a), "l"(b)); return d;
}
__device__ __forceinline__ u64 f2fma(u64 a, u64 b, u64 c) {
    u64 d; asm("fma.rn.f32x2 %0, %1, %2, %3;" : "=l"(d) : "l"(a), "l"(b), "l"(c)); return d;
}

__device__ __forceinline__ void cross3(const float* a, const float* b, float* o) {
    o[0] = a[1] * b[2] - a[2] * b[1];
    o[1] = a[2] * b[0] - a[0] * b[2];
    o[2] = a[0] * b[1] - a[1] * b[0];
}

__device__ __forceinline__ void load_adj(const float4 (*abuf)[32], int lane, int i,
                                         float* R, float* p) {
    float4 c0 = abuf[3 * i + 0][lane];
    float4 c1 = abuf[3 * i + 1][lane];
    float4 c2 = abuf[3 * i + 2][lane];
    R[0] = c0.x; R[1] = c0.y; R[2] = c0.z; R[3] = c0.w;
    R[4] = c1.x; R[5] = c1.y; R[6] = c1.z; R[7] = c1.w;
    R[8] = c2.x; p[0] = c2.y; p[1] = c2.z; p[2] = c2.w;
}

// AdT^T @ F : out_m = R^T (m + f x p) ; out_f = R^T f
__device__ __forceinline__ void adTF_rp(const float* R, const float* p,
                                        const float* in, float* out) {
    float m0 = in[0] + in[4] * p[2] - in[5] * p[1];
    float m1 = in[1] + in[5] * p[0] - in[3] * p[2];
    float m2 = in[2] + in[3] * p[1] - in[4] * p[0];
    out[0] = R[0] * m0 + R[3] * m1 + R[6] * m2;
    out[1] = R[1] * m0 + R[4] * m1 + R[7] * m2;
    out[2] = R[2] * m0 + R[5] * m1 + R[8] * m2;
    out[3] = R[0] * in[3] + R[3] * in[4] + R[6] * in[5];
    out[4] = R[1] * in[3] + R[4] * in[4] + R[7] * in[5];
    out[5] = R[2] * in[3] + R[5] * in[4] + R[8] * in[5];
}

__device__ __forceinline__ float dot6(const float* F, const float* w, const float* v) {
    return F[0] * w[0] + F[1] * w[1] + F[2] * w[2]
         + F[3] * v[0] + F[4] * v[1] + F[5] * v[2];
}

// packed AdT @ V on a pair state io[6]
__device__ __forceinline__ void adV_p2(const u64* Rp, const u64* pp, const u64* np,
                                       u64* io) {
    u64 a0 = f2fma(Rp[0], io[0], f2fma(Rp[1], io[1], f2mul(Rp[2], io[2])));
    u64 a1 = f2fma(Rp[3], io[0], f2fma(Rp[4], io[1], f2mul(Rp[5], io[2])));
    u64 a2 = f2fma(Rp[6], io[0], f2fma(Rp[7], io[1], f2mul(Rp[8], io[2])));
    u64 b0 = f2fma(Rp[0], io[3], f2fma(Rp[1], io[4], f2mul(Rp[2], io[5])));
    u64 b1 = f2fma(Rp[3], io[3], f2fma(Rp[4], io[4], f2mul(Rp[5], io[5])));
    u64 b2 = f2fma(Rp[6], io[3], f2fma(Rp[7], io[4], f2mul(Rp[8], io[5])));
    io[0] = a0; io[1] = a1; io[2] = a2;
    io[3] = f2fma(pp[1], a2, f2fma(np[2], a1, b0));
    io[4] = f2fma(pp[2], a0, f2fma(np[0], a2, b1));
    io[5] = f2fma(pp[0], a1, f2fma(np[1], a0, b2));
}

#define MTRI(i, j) Mtri[((i) * ((i) + 1)) / 2 + (j)]   // i >= j
__device__ __forceinline__ constexpr int colbase(int j) {
    return (j == 0) ? 7 : (j == 1) ? 14 : (j == 2) ? 20 : (j == 3) ? 25
         : (j == 4) ? 29 : (j == 5) ? 32 : 34;
}

// Build adjoint for joint i from q_i (scalar path), write (R,p) to shared.
__device__ __forceinline__ void build_adj(const Params& sp, float q, int i, int lane,
                                          float4 (*abuf)[32]) {
    float s, c;
    __sincosf(q, &s, &c);
    float th = -q, se = -s;
    const float* w = sp.w[i];
    const float* v = sp.v[i];
    float omc = 1.0f - c;
    float Re[9];
    Re[0] = c + omc * w[0] * w[0];
    Re[1] = se * (-w[2]) + omc * w[0] * w[1];
    Re[2] = se * ( w[1]) + omc * w[0] * w[2];
    Re[3] = se * ( w[2]) + omc * w[1] * w[0];
    Re[4] = c + omc * w[1] * w[1];
    Re[5] = se * (-w[0]) + omc * w[1] * w[2];
    Re[6] = se * (-w[1]) + omc * w[2] * w[0];
    Re[7] = se * ( w[0]) + omc * w[2] * w[1];
    Re[8] = c + omc * w[2] * w[2];
    float tms = th - se;
    float pe[3];
#pragma unroll
    for (int k = 0; k < 3; k++)
        pe[k] = th * v[k] + omc * sp.wxv[i][k] + tms * (w[k] * sp.wdv[i] - v[k]);
    const float* Rm = sp.Rm[i];
    float R[9];
#pragma unroll
    for (int r = 0; r < 3; r++)
#pragma unroll
        for (int cc = 0; cc < 3; cc++)
            R[r * 3 + cc] = Re[r * 3 + 0] * Rm[0 * 3 + cc]
                          + Re[r * 3 + 1] * Rm[1 * 3 + cc]
                          + Re[r * 3 + 2] * Rm[2 * 3 + cc];
    float p[3];
#pragma unroll
    for (int r = 0; r < 3; r++)
        p[r] = Re[r * 3 + 0] * sp.pm[i][0] + Re[r * 3 + 1] * sp.pm[i][1]
             + Re[r * 3 + 2] * sp.pm[i][2] + pe[r];
    abuf[3 * i + 0][lane] = make_float4(R[0], R[1], R[2], R[3]);
    abuf[3 * i + 1][lane] = make_float4(R[4], R[5], R[6], R[7]);
    abuf[3 * i + 2][lane] = make_float4(R[8], p[0], p[1], p[2]);
}

// Packed build of TWO adjoints (ia, ib) at once via f32x2.
__device__ __forceinline__ void build_adj2(const Params& sp, float qa, float qb,
                                           int ia, int ib, int lane,
                                           float4 (*abuf)[32]) {
    float sa, ca, sb, cb;
    __sincosf(qa, &sa, &ca);
    __sincosf(qb, &sb, &cb);
    u64 cP  = pk2(ca, cb);
    u64 seP = pk2(-sa, -sb);
    u64 thP = pk2(-qa, -qb);
    u64 wP[3], nwP[3], vP[3], wxvP[3];
#pragma unroll
    for (int c = 0; c < 3; c++) {
        wP[c]   = pk2(sp.w[ia][c],  sp.w[ib][c]);
        nwP[c]  = pk2(-sp.w[ia][c], -sp.w[ib][c]);
        vP[c]   = pk2(sp.v[ia][c],  sp.v[ib][c]);
        wxvP[c] = pk2(sp.wxv[ia][c], sp.wxv[ib][c]);
    }
    u64 wdvP = pk2(sp.wdv[ia], sp.wdv[ib]);
    const u64 NONE = pkb(-1.f);
    u64 omc = f2fma(cP, NONE, pkb(1.f));
    u64 ow0 = f2mul(omc, wP[0]);
    u64 ow1 = f2mul(omc, wP[1]);
    u64 ow2 = f2mul(omc, wP[2]);
    u64 Re[9];
    Re[0] = f2fma(ow0, wP[0], cP);
    Re[1] = f2fma(seP, nwP[2], f2mul(ow0, wP[1]));
    Re[2] = f2fma(seP, wP[1],  f2mul(ow0, wP[2]));
    Re[3] = f2fma(seP, wP[2],  f2mul(ow1, wP[0]));
    Re[4] = f2fma(ow1, wP[1], cP);
    Re[5] = f2fma(seP, nwP[0], f2mul(ow1, wP[2]));
    Re[6] = f2fma(seP, nwP[1], f2mul(ow2, wP[0]));
    Re[7] = f2fma(seP, wP[0],  f2mul(ow2, wP[1]));
    Re[8] = f2fma(ow2, wP[2], cP);
    u64 tms = f2fma(seP, NONE, thP);
    u64 pe[3];
#pragma unroll
    for (int k = 0; k < 3; k++) {
        u64 t1 = f2fma(wP[k], wdvP, f2mul(vP[k], NONE));   // w*wdv - v
        pe[k] = f2fma(tms, t1, f2fma(omc, wxvP[k], f2mul(thP, vP[k])));
    }
    u64 RmP[9], pmP[3];
#pragma unroll
    for (int c = 0; c < 9; c++) RmP[c] = pk2(sp.Rm[ia][c], sp.Rm[ib][c]);
#pragma unroll
    for (int c = 0; c < 3; c++) pmP[c] = pk2(sp.pm[ia][c], sp.pm[ib][c]);
    u64 R[9], p[3];
#pragma unroll
    for (int r = 0; r < 3; r++) {
#pragma unroll
        for (int cc = 0; cc < 3; cc++)
            R[r * 3 + cc] = f2fma(Re[r * 3 + 0], RmP[cc],
                            f2fma(Re[r * 3 + 1], RmP[3 + cc],
                            f2mul(Re[r * 3 + 2], RmP[6 + cc])));
        p[r] = f2fma(Re[r * 3 + 0], pmP[0],
               f2fma(Re[r * 3 + 1], pmP[1],
               f2fma(Re[r * 3 + 2], pmP[2], pe[r])));
    }
    float Ra[9], Rb[9], pa[3], pb[3];
#pragma unroll
    for (int k = 0; k < 9; k++) upk2(R[k], Ra[k], Rb[k]);
#pragma unroll
    for (int k = 0; k < 3; k++) upk2(p[k], pa[k], pb[k]);
    abuf[3 * ia + 0][lane] = make_float4(Ra[0], Ra[1], Ra[2], Ra[3]);
    abuf[3 * ia + 1][lane] = make_float4(Ra[4], Ra[5], Ra[6], Ra[7]);
    abuf[3 * ia + 2][lane] = make_float4(Ra[8], pa[0], pa[1], pa[2]);
    abuf[3 * ib + 0][lane] = make_float4(Rb[0], Rb[1], Rb[2], Rb[3]);
    abuf[3 * ib + 1][lane] = make_float4(Rb[4], Rb[5], Rb[6], Rb[7]);
    abuf[3 * ib + 2][lane] = make_float4(Rb[8], pb[0], pb[1], pb[2]);
}

// Pack adjoint coefficients for pair propagation.
__device__ __forceinline__ void pack_adj(const float* Rk, const float* pkv,
                                         u64* Rp, u64* pp, u64* np) {
#pragma unroll
    for (int c = 0; c < 9; c++) Rp[c] = pkb(Rk[c]);
#pragma unroll
    for (int c = 0; c < 3; c++) { pp[c] = pkb(pkv[c]); np[c] = pkb(-pkv[c]); }
}

// Insert screw S_k into its pair slot (lo for even k, hi for odd k), k<6.
__device__ __forceinline__ void insert_screw(const Params& sp, int k, u64 (*P)[6]) {
    const int t = k >> 1;
    if ((k & 1) == 0) {
#pragma unroll
        for (int c = 0; c < 3; c++) {
            P[t][c]     = pk2(sp.w[k][c], 0.f);
            P[t][3 + c] = pk2(sp.v[k][c], 0.f);
        }
    } else {
#pragma unroll
        for (int c = 0; c < 6; c++) {
            float lo, hi; upk2(P[t][c], lo, hi);
            float Sc = (c < 3) ? sp.w[k][c] : sp.v[k][c - 3];
            P[t][c] = pk2(lo, Sc);
        }
    }
}

// ---------------------------------------------------------------------------
// Fused kernel: role0 = bias packed (V,Vd) + scalar bwd; role1 = CRBA 2x2.
// Builds pair-packed; role0 builds 4 joints, role1 builds 3 (rebalance).
// ---------------------------------------------------------------------------
__global__ void __launch_bounds__(NTHREADS)
arm_kernel(const float* __restrict__ state, const float* __restrict__ action,
           const float* __restrict__ M_, const float* __restrict__ A_,
           const float* __restrict__ G_, const float* __restrict__ gravity,
           float* __restrict__ out) {
    __shared__ Params sp;
    __shared__ float4 abuf[21][32];    // adjoints (R,p) x 7 joints
    __shared__ float xch[35][32];      // bias (7) + lower-tri mass (28)

    const int tid = threadIdx.x;
    const int lane = tid & 31;
    const int role = tid >> 5;
    const int b = blockIdx.x * 32 + lane;

    // ---- per-block setup (threads 0..14) ----
    if (tid < 8) {
        int m = tid;
        const float* M = M_ + m * 16;
        float a1[3], a2[3], p[3];
#pragma unroll
        for (int r = 0; r < 3; r++) { a1[r] = M[r * 4 + 0]; a2[r] = M[r * 4 + 1]; p[r] = M[r * 4 + 3]; }
        float n1 = sqrtf(a1[0] * a1[0] + a1[1] * a1[1] + a1[2] * a1[2]);
        float b1[3] = { a1[0] / n1, a1[1] / n1, a1[2] / n1 };
        float d = a2[0] * b1[0] + a2[1] * b1[1] + a2[2] * b1[2];
        float a2o[3] = { a2[0] - d * b1[0], a2[1] - d * b1[1], a2[2] - d * b1[2] };
        float n2 = sqrtf(a2o[0] * a2o[0] + a2o[1] * a2o[1] + a2o[2] * a2o[2]);
        float b2[3] = { a2o[0] / n2, a2o[1] / n2, a2o[2] / n2 };
        float b3[3]; cross3(b1, b2, b3);
        float R[9];
#pragma unroll
        for (int r = 0; r < 3; r++) { R[r * 3 + 0] = b1[r]; R[r * 3 + 1] = b2[r]; R[r * 3 + 2] = b3[r]; }
#pragma unroll
        for (int k = 0; k < 9; k++) sp.Mr[m][k] = R[k];
#pragma unroll
        for (int r = 0; r < 3; r++) sp.Mp[m][r] = p[r];
        if (m < DOF) {
            float Rt_[9];
#pragma unroll
            for (int r = 0; r < 3; r++)
#pragma unroll
                for (int c = 0; c < 3; c++) Rt_[r * 3 + c] = R[c * 3 + r];
#pragma unroll
            for (int k = 0; k < 9; k++) sp.Rm[m][k] = Rt_[k];
#pragma unroll
            for (int r = 0; r < 3; r++)
                sp.pm[m][r] = -(Rt_[r * 3 + 0] * p[0] + Rt_[r * 3 + 1] * p[1] + Rt_[r * 3 + 2] * p[2]);
        }
    } else if (tid < 8 + DOF) {
        int j = tid - 8;
        const float* a = A_ + j * 6;
        float nw = sqrtf(a[0] * a[0] + a[1] * a[1] + a[2] * a[2]);
        float w[3] = { a[0] / nw, a[1] / nw, a[2] / nw };
        float v[3] = { a[3], a[4], a[5] };
#pragma unroll
        for (int k = 0; k < 3; k++) { sp.w[j][k] = w[k]; sp.v[j][k] = v[k]; }
        float wxv[3]; cross3(w, v, wxv);
#pragma unroll
        for (int k = 0; k < 3; k++) sp.wxv[j][k] = wxv[k];
        sp.wdv[j] = w[0] * v[0] + w[1] * v[1] + w[2] * v[2];
        float g0 = fabsf(G_[j * 4 + 0]);
        float g1 = fabsf(G_[j * 4 + 1]);
        float g2 = fabsf(G_[j * 4 + 2]);
        float g3 = fabsf(G_[j * 4 + 3]);
        sp.Gd[j][0] = g0; sp.Gd[j][1] = g1; sp.Gd[j][2] = g2;
        sp.Gd[j][3] = g3; sp.Gd[j][4] = g3; sp.Gd[j][5] = g3;
    }

    float q0[DOF], dq0[DOF], tq[DOF], g[3];
#pragma unroll
    for (int i = 0; i < DOF; i++) {
        q0[i]  = state[b * 14 + i];
        dq0[i] = state[b * 14 + DOF + i];
        tq[i]  = action[b * DOF + i] * ACTION_RANGE;
    }
    g[0] = gravity[0]; g[1] = gravity[1]; g[2] = gravity[2];
    __syncthreads();

    const float h = TSTEP;
    float qs[DOF], dqs[DOF], qc[DOF], dqc[DOF];
#pragma unroll
    for (int i = 0; i < DOF; i++) { qc[i] = q0[i]; dqc[i] = dq0[i]; qs[i] = 0.f; dqs[i] = 0.f; }

#pragma unroll 1
    for (int st = 0; st < 4; st++) {
        // ---- phase 0: builds (role0: pairs (0,1),(2,3) ; role1: (4,5)+6) ----
        if (role == 0) {
            build_adj2(sp, qc[0], qc[1], 0, 1, lane, abuf);
            build_adj2(sp, qc[2], qc[3], 2, 3, lane, abuf);
        } else {
            build_adj2(sp, qc[4], qc[5], 4, 5, lane, abuf);
            build_adj(sp, qc[6], 6, lane, abuf);
        }
        __syncthreads();   // sync1: abuf complete

        if (role == 0) {
            // ---- bias: packed (V,Vd) forward sweep + scalar backward sweep ----
            float fb[DOF][6];
            {
                u64 VP[6];
                VP[0] = pk2(0.f, 0.f); VP[1] = pk2(0.f, 0.f); VP[2] = pk2(0.f, 0.f);
                VP[3] = pk2(0.f, -g[0]); VP[4] = pk2(0.f, -g[1]); VP[5] = pk2(0.f, -g[2]);
#pragma unroll
                for (int k = 0; k < DOF; k++) {
                    float Rk[9], pkv[3];
                    load_adj(abuf, lane, k, Rk, pkv);
                    u64 Rp[9], pp[3], np[3];
                    pack_adj(Rk, pkv, Rp, pp, np);
                    adV_p2(Rp, pp, np, VP);          // (Ad V, Ad Vd)
                    float t[6], t2[6];
#pragma unroll
                    for (int c = 0; c < 6; c++) upk2(VP[c], t[c], t2[c]);
                    float Vn[6];
#pragma unroll
                    for (int c = 0; c < 3; c++) {
                        Vn[c]     = t[c]     + sp.w[k][c] * dqc[k];
                        Vn[3 + c] = t[3 + c] + sp.v[k][c] * dqc[k];
                    }
                    float aw[3], av1[3], av2[3];
                    cross3(&Vn[0], sp.w[k], aw);
                    cross3(&Vn[3], sp.w[k], av1);
                    cross3(&Vn[0], sp.v[k], av2);
                    float Vdn[6];
#pragma unroll
                    for (int c = 0; c < 3; c++) {
                        Vdn[c]     = t2[c]     + aw[c] * dqc[k];
                        Vdn[3 + c] = t2[3 + c] + (av1[c] + av2[c]) * dqc[k];
                    }
#pragma unroll
                    for (int c = 0; c < 6; c++) VP[c] = pk2(Vn[c], Vdn[c]);
                    float GV[6], GVd[6];
#pragma unroll
                    for (int c = 0; c < 6; c++) {
                        GV[c]  = sp.Gd[k][c] * Vn[c];
                        GVd[c] = sp.Gd[k][c] * Vdn[c];
                    }
                    float c1[3], c2[3], c3[3];
                    cross3(&Vn[0], &GV[0], c1);
                    cross3(&Vn[3], &GV[3], c2);
                    cross3(&Vn[0], &GV[3], c3);
#pragma unroll
                    for (int c = 0; c < 3; c++) {
                        fb[k][c]     = GVd[c]     + c1[c] + c2[c];
                        fb[k][3 + c] = GVd[3 + c] + c3[c];
                    }
                }
            }
            {
                float F[6];
#pragma unroll
                for (int c = 0; c < 6; c++) F[c] = fb[DOF - 1][c];
                xch[DOF - 1][lane] = dot6(F, sp.w[DOF - 1], sp.v[DOF - 1]);
#pragma unroll
                for (int ii = DOF - 2; ii >= 0; ii--) {
                    float Rk[9], pkv[3];
                    load_adj(abuf, lane, ii + 1, Rk, pkv);
                    float X[6];
                    adTF_rp(Rk, pkv, F, X);
#pragma unroll
                    for (int c = 0; c < 6; c++) F[c] = X[c] + fb[ii][c];
                    xch[ii][lane] = dot6(F, sp.w[ii], sp.v[ii]);
                }
            }
        } else {
            // ---- CRBA: packed chains + 2x2 block dots for all 28 entries ----
            u64 P[3][6];
            u64 D00 = 0, S00 = 0, D10 = 0, S10 = 0, D11 = 0, S11 = 0;
            u64 D20 = 0, S20 = 0, D21 = 0, S21 = 0, D22 = 0, S22 = 0;
            u64 M6p[3];
            float m66 = 0.f;
#pragma unroll
            for (int k = 0; k < DOF; k++) {
                float Rk[9], pkv[3];
                load_adj(abuf, lane, k, Rk, pkv);
                if (k >= 1) {
                    u64 Rp[9], pp[3], np[3];
                    pack_adj(Rk, pkv, Rp, pp, np);
#pragma unroll
                    for (int t3 = 0; t3 < 3; t3++)
                        if (2 * t3 < k) adV_p2(Rp, pp, np, P[t3]);
                }
                if (k < 6) insert_screw(sp, k, P);
                u64 Gdp[6];
#pragma unroll
                for (int c = 0; c < 6; c++) Gdp[c] = pkb(sp.Gd[k][c]);
                u64 Gp[3][6], Psw[3][6];
#pragma unroll
                for (int t3 = 0; t3 < 3; t3++)
                    if (2 * t3 <= k)
#pragma unroll
                        for (int c = 0; c < 6; c++) {
                            Gp[t3][c]  = f2mul(Gdp[c], P[t3][c]);
                            Psw[t3][c] = swap2(P[t3][c]);
                        }
#pragma unroll
                for (int c = 0; c < 6; c++) {
                    D00 = f2fma(P[0][c], Gp[0][c], D00);
                    S00 = f2fma(Psw[0][c], Gp[0][c], S00);
                }
                if (k >= 2)
#pragma unroll
                    for (int c = 0; c < 6; c++) {
                        D10 = f2fma(P[1][c], Gp[0][c], D10);
                        S10 = f2fma(Psw[1][c], Gp[0][c], S10);
                        D11 = f2fma(P[1][c], Gp[1][c], D11);
                        S11 = f2fma(Psw[1][c], Gp[1][c], S11);
                    }
                if (k >= 4)
#pragma unroll
                    for (int c = 0; c < 6; c++) {
                        D20 = f2fma(P[2][c], Gp[0][c], D20);
                        S20 = f2fma(Psw[2][c], Gp[0][c], S20);
                        D21 = f2fma(P[2][c], Gp[1][c], D21);
                        S21 = f2fma(Psw[2][c], Gp[1][c], S21);
                        D22 = f2fma(P[2][c], Gp[2][c], D22);
                        S22 = f2fma(Psw[2][c], Gp[2][c], S22);
                    }
                if (k == 6) {
                    float g6s6[6];
#pragma unroll
                    for (int c = 0; c < 6; c++) {
                        float s6c = (c < 3) ? sp.w[6][c] : sp.v[6][c - 3];
                        g6s6[c] = sp.Gd[6][c] * s6c;
                        m66 += g6s6[c] * s6c;
                    }
#pragma unroll
                    for (int t3 = 0; t3 < 3; t3++) {
                        u64 acc = 0;
#pragma unroll
                        for (int c = 0; c < 6; c++) acc = f2fma(P[t3][c], pkb(g6s6[c]), acc);
                        M6p[t3] = acc;
                    }
                }
            }
            float lo, hi;
            upk2(D00, lo, hi); xch[colbase(0) + 0][lane] = lo;   // M00
                               xch[colbase(1) + 0][lane] = hi;   // M11
            upk2(S00, lo, hi); xch[colbase(0) + 1][lane] = lo;   // M10
            upk2(D10, lo, hi); xch[colbase(0) + 2][lane] = lo;   // M20
                               xch[colbase(1) + 2][lane] = hi;   // M31
            upk2(S10, lo, hi); xch[colbase(0) + 3][lane] = lo;   // M30
                               xch[colbase(1) + 1][lane] = hi;   // M21
            upk2(D11, lo, hi); xch[colbase(2) + 0][lane] = lo;   // M22
                               xch[colbase(3) + 0][lane] = hi;   // M33
            upk2(S11, lo, hi); xch[colbase(2) + 1][lane] = lo;   // M32
            upk2(D20, lo, hi); xch[colbase(0) + 4][lane] = lo;   // M40
                               xch[colbase(1) + 4][lane] = hi;   // M51
            upk2(S20, lo, hi); xch[colbase(0) + 5][lane] = lo;   // M50
                               xch[colbase(1) + 3][lane] = hi;   // M41
            upk2(D21, lo, hi); xch[colbase(2) + 2][lane] = lo;   // M42
                               xch[colbase(3) + 2][lane] = hi;   // M53
            upk2(S21, lo, hi); xch[colbase(2) + 3][lane] = lo;   // M52
                               xch[colbase(3) + 1][lane] = hi;   // M43
            upk2(D22, lo, hi); xch[colbase(4) + 0][lane] = lo;   // M44
                               xch[colbase(5) + 0][lane] = hi;   // M55
            upk2(S22, lo, hi); xch[colbase(4) + 1][lane] = lo;   // M54
            upk2(M6p[0], lo, hi); xch[colbase(0) + 6][lane] = lo; // M60
                                  xch[colbase(1) + 5][lane] = hi; // M61
            upk2(M6p[1], lo, hi); xch[colbase(2) + 4][lane] = lo; // M62
                                  xch[colbase(3) + 3][lane] = hi; // M63
            upk2(M6p[2], lo, hi); xch[colbase(4) + 2][lane] = lo; // M64
                                  xch[colbase(5) + 1][lane] = hi; // M65
            xch[colbase(6) + 0][lane] = m66;                      // M66
        }
        __syncthreads();   // sync2: xch complete

        // ---- solve + RK update (duplicated in both roles) ----
        float bias[DOF], Mtri[(DOF * (DOF + 1)) / 2];
#pragma unroll
        for (int i = 0; i < DOF; i++) bias[i] = xch[i][lane];
#pragma unroll
        for (int j = 0; j < DOF; j++)
#pragma unroll
            for (int i = j; i < DOF; i++)
                MTRI(i, j) = xch[colbase(j) + i - j][lane];

        float x[DOF], invd[DOF];
#pragma unroll
        for (int i = 0; i < DOF; i++) x[i] = tq[i] - bias[i];
#pragma unroll
        for (int k = 0; k < DOF; k++) {
            float inv = __fdividef(1.0f, MTRI(k, k));
            invd[k] = inv;
            float fk[DOF];
#pragma unroll
            for (int i = k + 1; i < DOF; i++) fk[i] = MTRI(i, k) * inv;
#pragma unroll
            for (int i = k + 1; i < DOF; i++) {
                x[i] -= fk[i] * x[k];
#pragma unroll
                for (int jj = k + 1; jj <= i; jj++)
                    MTRI(i, jj) -= fk[i] * MTRI(jj, k);
            }
#pragma unroll
            for (int i = k + 1; i < DOF; i++) MTRI(i, k) = fk[i];
        }
#pragma unroll
        for (int i = 0; i < DOF; i++) x[i] *= invd[i];
#pragma unroll
        for (int i = DOF - 2; i >= 0; i--) {
            float s = x[i];
#pragma unroll
            for (int jj = i + 1; jj < DOF; jj++) s -= MTRI(jj, i) * x[jj];
            x[i] = s;
        }

        float wk = (st == 1 || st == 2) ? 2.0f : 1.0f;
        float cc = (st == 2) ? 1.0f : 0.5f;
#pragma unroll
        for (int i = 0; i < DOF; i++) {
            qs[i]  += wk * dqc[i];
            dqs[i] += wk * x[i];
            qc[i]  = q0[i]  + cc * h * dqc[i];
            dqc[i] = dq0[i] + cc * h * x[i];
        }
    }

    const float PI = 3.14159265358979323846f;
    const float TWO_PI = 6.28318530717958647692f;
    float qn[DOF];
#pragma unroll
    for (int i = 0; i < DOF; i++) {
        float qv = q0[i] + (h / 6.0f) * qs[i];
        float t = qv;
        if (qv >= PI) t = qv - TWO_PI;
        else if (qv < -PI) t = qv + TWO_PI;
        qn[i] = t;
        if (role == 0) {
            out[b * 14 + i] = qn[i];
        } else {
            float dv = dq0[i] + (h / 6.0f) * dqs[i];
            dv = fminf(fmaxf(dv, -MAX_VEL), MAX_VEL);
            out[b * 14 + DOF + i] = dv;
        }
    }

    // ---- FK: row `role` of T propagates independently; ee component = role ----
    float TRr[3] = { role == 0 ? 1.f : 0.f, role == 0 ? 0.f : 1.f, 0.f };
    float Tpr = 0.f;
#pragma unroll
    for (int i = 0; i < DOF; i++) {
        float s, c;
        __sincosf(qn[i], &s, &c);
        const float* w = sp.w[i];
        const float* v = sp.v[i];
        float omc = 1.0f - c;
        float Re[9];
        Re[0] = c + omc * w[0] * w[0];
        Re[1] = s * (-w[2]) + omc * w[0] * w[1];
        Re[2] = s * ( w[1]) + omc * w[0] * w[2];
        Re[3] = s * ( w[2]) + omc * w[1] * w[0];
        Re[4] = c + omc * w[1] * w[1];
        Re[5] = s * (-w[0]) + omc * w[1] * w[2];
        Re[6] = s * (-w[1]) + omc * w[2] * w[0];
        Re[7] = s * ( w[0]) + omc * w[2] * w[1];
        Re[8] = c + omc * w[2] * w[2];
        float th = qn[i];
        float tms = th - s;
        float pe[3];
#pragma unroll
        for (int k = 0; k < 3; k++)
            pe[k] = th * v[k] + omc * sp.wxv[i][k] + tms * (w[k] * sp.wdv[i] - v[k]);
        const float* Mr = sp.Mr[i];
        const float* Mp = sp.Mp[i];
        float Tm[3];
#pragma unroll
        for (int cc2 = 0; cc2 < 3; cc2++)
            Tm[cc2] = TRr[0] * Mr[0 * 3 + cc2] + TRr[1] * Mr[1 * 3 + cc2] + TRr[2] * Mr[2 * 3 + cc2];
        Tpr += TRr[0] * Mp[0] + TRr[1] * Mp[1] + TRr[2] * Mp[2]
             + Tm[0] * pe[0] + Tm[1] * pe[1] + Tm[2] * pe[2];
        float nTR[3];
#pragma unroll
        for (int cc2 = 0; cc2 < 3; cc2++)
            nTR[cc2] = Tm[0] * Re[0 * 3 + cc2] + Tm[1] * Re[1 * 3 + cc2] + Tm[2] * Re[2 * 3 + cc2];
        TRr[0] = nTR[0]; TRr[1] = nTR[1]; TRr[2] = nTR[2];
    }
    const float* Mp7 = sp.Mp[DOF];
    float e = TRr[0] * Mp7[0] + TRr[1] * Mp7[1] + TRr[2] * Mp7[2] + Tpr;
    out[BATCH * 14 + b * 2 + role] = e;
}

extern "C" void kernel_launch(void* const* d_in, const int* in_sizes, int n_in,
                              void* d_out, int out_size) {
    const float* state   = (const float*)d_in[0];
    const float* action  = (const float*)d_in[1];
    const float* M_      = (const float*)d_in[2];
    const float* A_      = (const float*)d_in[3];
    const float* G_      = (const float*)d_in[4];
    const float* gravity = (const float*)d_in[5];
    float* out = (float*)d_out;

    arm_kernel<<<BATCH / 32, NTHREADS>>>(state, action, M_, A_, G_, gravity, out);
}

// round 17
// speedup vs baseline: 1.0960x; 1.0960x over previous
#include <cuda_runtime.h>
#include <math.h>

#define DOF 7
#define BATCH 16384
#define NTHREADS 64          // 2 warps per block, 32 elements/block
#define ACTION_RANGE 50.0f
#define MAX_VEL 20.0f
#define TSTEP 0.1f

typedef unsigned long long u64;

struct Params {
    float w[DOF][3];
    float v[DOF][3];
    float wxv[DOF][3];
    float wdv[DOF];
    float Rm[DOF][9];     // trans_inv(Mlist[i]) rotation
    float pm[DOF][3];     // trans_inv(Mlist[i]) translation
    float Gd[DOF][6];
    float Mr[DOF + 1][9]; // Mlist rotations (FK)
    float Mp[DOF + 1][3]; // Mlist translations (FK)
};

// ---------------- packed f32x2 helpers ----------------
__device__ __forceinline__ u64 pk2(float lo, float hi) {
    u64 r; asm("mov.b64 %0, {%1,%2};" : "=l"(r) : "f"(lo), "f"(hi)); return r;
}
__device__ __forceinline__ u64 pkb(float x) { return pk2(x, x); }
__device__ __forceinline__ void upk2(u64 v, float& lo, float& hi) {
    asm("mov.b64 {%0,%1}, %2;" : "=f"(lo), "=f"(hi) : "l"(v));
}
__device__ __forceinline__ u64 swap2(u64 v) {
    float lo, hi; upk2(v, lo, hi); return pk2(hi, lo);
}
__device__ __forceinline__ u64 f2mul(u64 a, u64 b) {
    u64 d; asm("mul.rn.f32x2 %0, %1, %2;" : "=l"(d) : "l"(a), "l"(b)); return d;
}
__device__ __forceinline__ u64 f2fma(u64 a, u64 b, u64 c) {
    u64 d; asm("fma.rn.f32x2 %0, %1, %2, %3;" : "=l"(d) : "l"(a), "l"(b), "l"(c)); return d;
}

__device__ __forceinline__ void cross3(const float* a, const float* b, float* o) {
    o[0] = a[1] * b[2] - a[2] * b[1];
    o[1] = a[2] * b[0] - a[0] * b[2];
    o[2] = a[0] * b[1] - a[1] * b[0];
}

__device__ __forceinline__ void load_adj(const float4 (*abuf)[32], int lane, int i,
                                         float* R, float* p) {
    float4 c0 = abuf[3 * i + 0][lane];
    float4 c1 = abuf[3 * i + 1][lane];
    float4 c2 = abuf[3 * i + 2][lane];
    R[0] = c0.x; R[1] = c0.y; R[2] = c0.z; R[3] = c0.w;
    R[4] = c1.x; R[5] = c1.y; R[6] = c1.z; R[7] = c1.w;
    R[8] = c2.x; p[0] = c2.y; p[1] = c2.z; p[2] = c2.w;
}

// AdT^T @ F : out_m = R^T (m + f x p) ; out_f = R^T f
__device__ __forceinline__ void adTF_rp(const float* R, const float* p,
                                        const float* in, float* out) {
    float m0 = in[0] + in[4] * p[2] - in[5] * p[1];
    float m1 = in[1] + in[5] * p[0] - in[3] * p[2];
    float m2 = in[2] + in[3] * p[1] - in[4] * p[0];
    out[0] = R[0] * m0 + R[3] * m1 + R[6] * m2;
    out[1] = R[1] * m0 + R[4] * m1 + R[7] * m2;
    out[2] = R[2] * m0 + R[5] * m1 + R[8] * m2;
    out[3] = R[0] * in[3] + R[3] * in[4] + R[6] * in[5];
    out[4] = R[1] * in[3] + R[4] * in[4] + R[7] * in[5];
    out[5] = R[2] * in[3] + R[5] * in[4] + R[8] * in[5];
}

__device__ __forceinline__ float dot6(const float* F, const float* w, const float* v) {
    return F[0] * w[0] + F[1] * w[1] + F[2] * w[2]
         + F[3] * v[0] + F[4] * v[1] + F[5] * v[2];
}

// packed AdT @ V on a pair state io[6]
__device__ __forceinline__ void adV_p2(const u64* Rp, const u64* pp, const u64* np,
                                       u64* io) {
    u64 a0 = f2fma(Rp[0], io[0], f2fma(Rp[1], io[1], f2mul(Rp[2], io[2])));
    u64 a1 = f2fma(Rp[3], io[0], f2fma(Rp[4], io[1], f2mul(Rp[5], io[2])));
    u64 a2 = f2fma(Rp[6], io[0], f2fma(Rp[7], io[1], f2mul(Rp[8], io[2])));
    u64 b0 = f2fma(Rp[0], io[3], f2fma(Rp[1], io[4], f2mul(Rp[2], io[5])));
    u64 b1 = f2fma(Rp[3], io[3], f2fma(Rp[4], io[4], f2mul(Rp[5], io[5])));
    u64 b2 = f2fma(Rp[6], io[3], f2fma(Rp[7], io[4], f2mul(Rp[8], io[5])));
    io[0] = a0; io[1] = a1; io[2] = a2;
    io[3] = f2fma(pp[1], a2, f2fma(np[2], a1, b0));
    io[4] = f2fma(pp[2], a0, f2fma(np[0], a2, b1));
    io[5] = f2fma(pp[0], a1, f2fma(np[1], a0, b2));
}

#define MTRI(i, j) Mtri[((i) * ((i) + 1)) / 2 + (j)]   // i >= j
__device__ __forceinline__ constexpr int colbase(int j) {
    return (j == 0) ? 7 : (j == 1) ? 14 : (j == 2) ? 20 : (j == 3) ? 25
         : (j == 4) ? 29 : (j == 5) ? 32 : 34;
}

// Build adjoint for joint i from q_i, write (R,p) to shared.
__device__ __forceinline__ void build_adj(const Params& sp, float q, int i, int lane,
                                          float4 (*abuf)[32]) {
    float s, c;
    __sincosf(q, &s, &c);
    float th = -q, se = -s;
    const float* w = sp.w[i];
    const float* v = sp.v[i];
    float omc = 1.0f - c;
    float Re[9];
    Re[0] = c + omc * w[0] * w[0];
    Re[1] = se * (-w[2]) + omc * w[0] * w[1];
    Re[2] = se * ( w[1]) + omc * w[0] * w[2];
    Re[3] = se * ( w[2]) + omc * w[1] * w[0];
    Re[4] = c + omc * w[1] * w[1];
    Re[5] = se * (-w[0]) + omc * w[1] * w[2];
    Re[6] = se * (-w[1]) + omc * w[2] * w[0];
    Re[7] = se * ( w[0]) + omc * w[2] * w[1];
    Re[8] = c + omc * w[2] * w[2];
    float tms = th - se;
    float pe[3];
#pragma unroll
    for (int k = 0; k < 3; k++)
        pe[k] = th * v[k] + omc * sp.wxv[i][k] + tms * (w[k] * sp.wdv[i] - v[k]);
    const float* Rm = sp.Rm[i];
    float R[9];
#pragma unroll
    for (int r = 0; r < 3; r++)
#pragma unroll
        for (int cc = 0; cc < 3; cc++)
            R[r * 3 + cc] = Re[r * 3 + 0] * Rm[0 * 3 + cc]
                          + Re[r * 3 + 1] * Rm[1 * 3 + cc]
                          + Re[r * 3 + 2] * Rm[2 * 3 + cc];
    float p[3];
#pragma unroll
    for (int r = 0; r < 3; r++)
        p[r] = Re[r * 3 + 0] * sp.pm[i][0] + Re[r * 3 + 1] * sp.pm[i][1]
             + Re[r * 3 + 2] * sp.pm[i][2] + pe[r];
    abuf[3 * i + 0][lane] = make_float4(R[0], R[1], R[2], R[3]);
    abuf[3 * i + 1][lane] = make_float4(R[4], R[5], R[6], R[7]);
    abuf[3 * i + 2][lane] = make_float4(R[8], p[0], p[1], p[2]);
}

// Pack adjoint coefficients for pair propagation.
__device__ __forceinline__ void pack_adj(const float* Rk, const float* pkv,
                                         u64* Rp, u64* pp, u64* np) {
#pragma unroll
    for (int c = 0; c < 9; c++) Rp[c] = pkb(Rk[c]);
#pragma unroll
    for (int c = 0; c < 3; c++) { pp[c] = pkb(pkv[c]); np[c] = pkb(-pkv[c]); }
}

// Insert screw S_k into its pair slot (lo for even k, hi for odd k), k<6.
__device__ __forceinline__ void insert_screw(const Params& sp, int k, u64 (*P)[6]) {
    const int t = k >> 1;
    if ((k & 1) == 0) {
#pragma unroll
        for (int c = 0; c < 3; c++) {
            P[t][c]     = pk2(sp.w[k][c], 0.f);
            P[t][3 + c] = pk2(sp.v[k][c], 0.f);
        }
    } else {
#pragma unroll
        for (int c = 0; c < 6; c++) {
            float lo, hi; upk2(P[t][c], lo, hi);
            float Sc = (c < 3) ? sp.w[k][c] : sp.v[k][c - 3];
            P[t][c] = pk2(lo, Sc);
        }
    }
}

// ---------------------------------------------------------------------------
// Fused kernel: role0 = bias with packed (V,Vd) fwd sweep + scalar bwd sweep;
//               role1 = CRBA 2x2 block dots (all 28 mass entries).
// ---------------------------------------------------------------------------
__global__ void __launch_bounds__(NTHREADS)
arm_kernel(const float* __restrict__ state, const float* __restrict__ action,
           const float* __restrict__ M_, const float* __restrict__ A_,
           const float* __restrict__ G_, const float* __restrict__ gravity,
           float* __restrict__ out) {
    __shared__ Params sp;
    __shared__ float4 abuf[21][32];    // adjoints (R,p) x 7 joints
    __shared__ float xch[35][32];      // bias (7) + lower-tri mass (28)

    const int tid = threadIdx.x;
    const int lane = tid & 31;
    const int role = tid >> 5;
    const int b = blockIdx.x * 32 + lane;

    // ---- per-block setup (threads 0..14) ----
    if (tid < 8) {
        int m = tid;
        const float* M = M_ + m * 16;
        float a1[3], a2[3], p[3];
#pragma unroll
        for (int r = 0; r < 3; r++) { a1[r] = M[r * 4 + 0]; a2[r] = M[r * 4 + 1]; p[r] = M[r * 4 + 3]; }
        float n1 = sqrtf(a1[0] * a1[0] + a1[1] * a1[1] + a1[2] * a1[2]);
        float b1[3] = { a1[0] / n1, a1[1] / n1, a1[2] / n1 };
        float d = a2[0] * b1[0] + a2[1] * b1[1] + a2[2] * b1[2];
        float a2o[3] = { a2[0] - d * b1[0], a2[1] - d * b1[1], a2[2] - d * b1[2] };
        float n2 = sqrtf(a2o[0] * a2o[0] + a2o[1] * a2o[1] + a2o[2] * a2o[2]);
        float b2[3] = { a2o[0] / n2, a2o[1] / n2, a2o[2] / n2 };
        float b3[3]; cross3(b1, b2, b3);
        float R[9];
#pragma unroll
        for (int r = 0; r < 3; r++) { R[r * 3 + 0] = b1[r]; R[r * 3 + 1] = b2[r]; R[r * 3 + 2] = b3[r]; }
#pragma unroll
        for (int k = 0; k < 9; k++) sp.Mr[m][k] = R[k];
#pragma unroll
        for (int r = 0; r < 3; r++) sp.Mp[m][r] = p[r];
        if (m < DOF) {
            float Rt_[9];
#pragma unroll
            for (int r = 0; r < 3; r++)
#pragma unroll
                for (int c = 0; c < 3; c++) Rt_[r * 3 + c] = R[c * 3 + r];
#pragma unroll
            for (int k = 0; k < 9; k++) sp.Rm[m][k] = Rt_[k];
#pragma unroll
            for (int r = 0; r < 3; r++)
                sp.pm[m][r] = -(Rt_[r * 3 + 0] * p[0] + Rt_[r * 3 + 1] * p[1] + Rt_[r * 3 + 2] * p[2]);
        }
    } else if (tid < 8 + DOF) {
        int j = tid - 8;
        const float* a = A_ + j * 6;
        float nw = sqrtf(a[0] * a[0] + a[1] * a[1] + a[2] * a[2]);
        float w[3] = { a[0] / nw, a[1] / nw, a[2] / nw };
        float v[3] = { a[3], a[4], a[5] };
#pragma unroll
        for (int k = 0; k < 3; k++) { sp.w[j][k] = w[k]; sp.v[j][k] = v[k]; }
        float wxv[3]; cross3(w, v, wxv);
#pragma unroll
        for (int k = 0; k < 3; k++) sp.wxv[j][k] = wxv[k];
        sp.wdv[j] = w[0] * v[0] + w[1] * v[1] + w[2] * v[2];
        float g0 = fabsf(G_[j * 4 + 0]);
        float g1 = fabsf(G_[j * 4 + 1]);
        float g2 = fabsf(G_[j * 4 + 2]);
        float g3 = fabsf(G_[j * 4 + 3]);
        sp.Gd[j][0] = g0; sp.Gd[j][1] = g1; sp.Gd[j][2] = g2;
        sp.Gd[j][3] = g3; sp.Gd[j][4] = g3; sp.Gd[j][5] = g3;
    }

    float q0[DOF], dq0[DOF], tq[DOF], g[3];
#pragma unroll
    for (int i = 0; i < DOF; i++) {
        q0[i]  = state[b * 14 + i];
        dq0[i] = state[b * 14 + DOF + i];
        tq[i]  = action[b * DOF + i] * ACTION_RANGE;
    }
    g[0] = gravity[0]; g[1] = gravity[1]; g[2] = gravity[2];
    __syncthreads();

    const float h = TSTEP;
    float qs[DOF], dqs[DOF], qc[DOF], dqc[DOF];
#pragma unroll
    for (int i = 0; i < DOF; i++) { qc[i] = q0[i]; dqc[i] = dq0[i]; qs[i] = 0.f; dqs[i] = 0.f; }

#pragma unroll 1
    for (int st = 0; st < 4; st++) {
        // ---- phase 0: builds (role0: 0-2 ; role1: 3-6) ----
        if (role == 0) {
            build_adj(sp, qc[0], 0, lane, abuf);
            build_adj(sp, qc[1], 1, lane, abuf);
            build_adj(sp, qc[2], 2, lane, abuf);
        } else {
            build_adj(sp, qc[3], 3, lane, abuf);
            build_adj(sp, qc[4], 4, lane, abuf);
            build_adj(sp, qc[5], 5, lane, abuf);
            build_adj(sp, qc[6], 6, lane, abuf);
        }
        __syncthreads();   // sync1: abuf complete

        if (role == 0) {
            // ---- bias: packed (V,Vd) forward sweep + scalar backward sweep ----
            float fb[DOF][6];
            {
                u64 VP[6];
                VP[0] = pk2(0.f, 0.f); VP[1] = pk2(0.f, 0.f); VP[2] = pk2(0.f, 0.f);
                VP[3] = pk2(0.f, -g[0]); VP[4] = pk2(0.f, -g[1]); VP[5] = pk2(0.f, -g[2]);
#pragma unroll
                for (int k = 0; k < DOF; k++) {
                    float Rk[9], pkv[3];
                    load_adj(abuf, lane, k, Rk, pkv);
                    u64 Rp[9], pp[3], np[3];
                    pack_adj(Rk, pkv, Rp, pp, np);
                    adV_p2(Rp, pp, np, VP);          // (Ad V, Ad Vd)
                    float t[6], t2[6];
#pragma unroll
                    for (int c = 0; c < 6; c++) upk2(VP[c], t[c], t2[c]);
                    float Vn[6];
#pragma unroll
                    for (int c = 0; c < 3; c++) {
                        Vn[c]     = t[c]     + sp.w[k][c] * dqc[k];
                        Vn[3 + c] = t[3 + c] + sp.v[k][c] * dqc[k];
                    }
                    float aw[3], av1[3], av2[3];
                    cross3(&Vn[0], sp.w[k], aw);
                    cross3(&Vn[3], sp.w[k], av1);
                    cross3(&Vn[0], sp.v[k], av2);
                    float Vdn[6];
#pragma unroll
                    for (int c = 0; c < 3; c++) {
                        Vdn[c]     = t2[c]     + aw[c] * dqc[k];
                        Vdn[3 + c] = t2[3 + c] + (av1[c] + av2[c]) * dqc[k];
                    }
#pragma unroll
                    for (int c = 0; c < 6; c++) VP[c] = pk2(Vn[c], Vdn[c]);
                    float GV[6], GVd[6];
#pragma unroll
                    for (int c = 0; c < 6; c++) {
                        GV[c]  = sp.Gd[k][c] * Vn[c];
                        GVd[c] = sp.Gd[k][c] * Vdn[c];
                    }
                    float c1[3], c2[3], c3[3];
                    cross3(&Vn[0], &GV[0], c1);
                    cross3(&Vn[3], &GV[3], c2);
                    cross3(&Vn[0], &GV[3], c3);
#pragma unroll
                    for (int c = 0; c < 3; c++) {
                        fb[k][c]     = GVd[c]     + c1[c] + c2[c];
                        fb[k][3 + c] = GVd[3 + c] + c3[c];
                    }
                }
            }
            {
                float F[6];
#pragma unroll
                for (int c = 0; c < 6; c++) F[c] = fb[DOF - 1][c];
                xch[DOF - 1][lane] = dot6(F, sp.w[DOF - 1], sp.v[DOF - 1]);
#pragma unroll
                for (int ii = DOF - 2; ii >= 0; ii--) {
                    float Rk[9], pkv[3];
                    load_adj(abuf, lane, ii + 1, Rk, pkv);
                    float X[6];
                    adTF_rp(Rk, pkv, F, X);
#pragma unroll
                    for (int c = 0; c < 6; c++) F[c] = X[c] + fb[ii][c];
                    xch[ii][lane] = dot6(F, sp.w[ii], sp.v[ii]);
                }
            }
        } else {
            // ---- CRBA: packed chains + 2x2 block dots for all 28 entries ----
            u64 P[3][6];
            u64 D00 = 0, S00 = 0, D10 = 0, S10 = 0, D11 = 0, S11 = 0;
            u64 D20 = 0, S20 = 0, D21 = 0, S21 = 0, D22 = 0, S22 = 0;
            u64 M6p[3];
            float m66 = 0.f;
#pragma unroll
            for (int k = 0; k < DOF; k++) {
                float Rk[9], pkv[3];
                load_adj(abuf, lane, k, Rk, pkv);
                if (k >= 1) {
                    u64 Rp[9], pp[3], np[3];
                    pack_adj(Rk, pkv, Rp, pp, np);
#pragma unroll
                    for (int t3 = 0; t3 < 3; t3++)
                        if (2 * t3 < k) adV_p2(Rp, pp, np, P[t3]);
                }
                if (k < 6) insert_screw(sp, k, P);
                u64 Gdp[6];
#pragma unroll
                for (int c = 0; c < 6; c++) Gdp[c] = pkb(sp.Gd[k][c]);
                u64 Gp[3][6], Psw[3][6];
#pragma unroll
                for (int t3 = 0; t3 < 3; t3++)
                    if (2 * t3 <= k)
#pragma unroll
                        for (int c = 0; c < 6; c++) {
                            Gp[t3][c]  = f2mul(Gdp[c], P[t3][c]);
                            Psw[t3][c] = swap2(P[t3][c]);
                        }
#pragma unroll
                for (int c = 0; c < 6; c++) {
                    D00 = f2fma(P[0][c], Gp[0][c], D00);
                    S00 = f2fma(Psw[0][c], Gp[0][c], S00);
                }
                if (k >= 2)
#pragma unroll
                    for (int c = 0; c < 6; c++) {
                        D10 = f2fma(P[1][c], Gp[0][c], D10);
                        S10 = f2fma(Psw[1][c], Gp[0][c], S10);
                        D11 = f2fma(P[1][c], Gp[1][c], D11);
                        S11 = f2fma(Psw[1][c], Gp[1][c], S11);
                    }
                if (k >= 4)
#pragma unroll
                    for (int c = 0; c < 6; c++) {
                        D20 = f2fma(P[2][c], Gp[0][c], D20);
                        S20 = f2fma(Psw[2][c], Gp[0][c], S20);
                        D21 = f2fma(P[2][c], Gp[1][c], D21);
                        S21 = f2fma(Psw[2][c], Gp[1][c], S21);
                        D22 = f2fma(P[2][c], Gp[2][c], D22);
                        S22 = f2fma(Psw[2][c], Gp[2][c], S22);
                    }
                if (k == 6) {
                    float g6s6[6];
#pragma unroll
                    for (int c = 0; c < 6; c++) {
                        float s6c = (c < 3) ? sp.w[6][c] : sp.v[6][c - 3];
                        g6s6[c] = sp.Gd[6][c] * s6c;
                        m66 += g6s6[c] * s6c;
                    }
#pragma unroll
                    for (int t3 = 0; t3 < 3; t3++) {
                        u64 acc = 0;
#pragma unroll
                        for (int c = 0; c < 6; c++) acc = f2fma(P[t3][c], pkb(g6s6[c]), acc);
                        M6p[t3] = acc;
                    }
                }
            }
            float lo, hi;
            upk2(D00, lo, hi); xch[colbase(0) + 0][lane] = lo;   // M00
                               xch[colbase(1) + 0][lane] = hi;   // M11
            upk2(S00, lo, hi); xch[colbase(0) + 1][lane] = lo;   // M10
            upk2(D10, lo, hi); xch[colbase(0) + 2][lane] = lo;   // M20
                               xch[colbase(1) + 2][lane] = hi;   // M31
            upk2(S10, lo, hi); xch[colbase(0) + 3][lane] = lo;   // M30
                               xch[colbase(1) + 1][lane] = hi;   // M21
            upk2(D11, lo, hi); xch[colbase(2) + 0][lane] = lo;   // M22
                               xch[colbase(3) + 0][lane] = hi;   // M33
            upk2(S11, lo, hi); xch[colbase(2) + 1][lane] = lo;   // M32
            upk2(D20, lo, hi); xch[colbase(0) + 4][lane] = lo;   // M40
                               xch[colbase(1) + 4][lane] = hi;   // M51
            upk2(S20, lo, hi); xch[colbase(0) + 5][lane] = lo;   // M50
                               xch[colbase(1) + 3][lane] = hi;   // M41
            upk2(D21, lo, hi); xch[colbase(2) + 2][lane] = lo;   // M42
                               xch[colbase(3) + 2][lane] = hi;   // M53
            upk2(S21, lo, hi); xch[colbase(2) + 3][lane] = lo;   // M52
                               xch[colbase(3) + 1][lane] = hi;   // M43
            upk2(D22, lo, hi); xch[colbase(4) + 0][lane] = lo;   // M44
                               xch[colbase(5) + 0][lane] = hi;   // M55
            upk2(S22, lo, hi); xch[colbase(4) + 1][lane] = lo;   // M54
            upk2(M6p[0], lo, hi); xch[colbase(0) + 6][lane] = lo; // M60
                                  xch[colbase(1) + 5][lane] = hi; // M61
            upk2(M6p[1], lo, hi); xch[colbase(2) + 4][lane] = lo; // M62
                                  xch[colbase(3) + 3][lane] = hi; // M63
            upk2(M6p[2], lo, hi); xch[colbase(4) + 2][lane] = lo; // M64
                                  xch[colbase(5) + 1][lane] = hi; // M65
            xch[colbase(6) + 0][lane] = m66;                      // M66
        }
        __syncthreads();   // sync2: xch complete

        // ---- solve + RK update (duplicated in both roles) ----
        float bias[DOF], Mtri[(DOF * (DOF + 1)) / 2];
#pragma unroll
        for (int i = 0; i < DOF; i++) bias[i] = xch[i][lane];
#pragma unroll
        for (int j = 0; j < DOF; j++)
#pragma unroll
            for (int i = j; i < DOF; i++)
                MTRI(i, j) = xch[colbase(j) + i - j][lane];

        float x[DOF], invd[DOF];
#pragma unroll
        for (int i = 0; i < DOF; i++) x[i] = tq[i] - bias[i];
#pragma unroll
        for (int k = 0; k < DOF; k++) {
            float inv = __fdividef(1.0f, MTRI(k, k));
            invd[k] = inv;
            float fk[DOF];
#pragma unroll
            for (int i = k + 1; i < DOF; i++) fk[i] = MTRI(i, k) * inv;
#pragma unroll
            for (int i = k + 1; i < DOF; i++) {
                x[i] -= fk[i] * x[k];
#pragma unroll
                for (int jj = k + 1; jj <= i; jj++)
                    MTRI(i, jj) -= fk[i] * MTRI(jj, k);
            }
#pragma unroll
            for (int i = k + 1; i < DOF; i++) MTRI(i, k) = fk[i];
        }
#pragma unroll
        for (int i = 0; i < DOF; i++) x[i] *= invd[i];
#pragma unroll
        for (int i = DOF - 2; i >= 0; i--) {
            float s = x[i];
#pragma unroll
            for (int jj = i + 1; jj < DOF; jj++) s -= MTRI(jj, i) * x[jj];
            x[i] = s;
        }

        float wk = (st == 1 || st == 2) ? 2.0f : 1.0f;
        float cc = (st == 2) ? 1.0f : 0.5f;
#pragma unroll
        for (int i = 0; i < DOF; i++) {
            qs[i]  += wk * dqc[i];
            dqs[i] += wk * x[i];
            qc[i]  = q0[i]  + cc * h * dqc[i];
            dqc[i] = dq0[i] + cc * h * x[i];
        }
    }

    const float PI = 3.14159265358979323846f;
    const float TWO_PI = 6.28318530717958647692f;
    float qn[DOF];
#pragma unroll
    for (int i = 0; i < DOF; i++) {
        float qv = q0[i] + (h / 6.0f) * qs[i];
        float t = qv;
        if (qv >= PI) t = qv - TWO_PI;
        else if (qv < -PI) t = qv + TWO_PI;
        qn[i] = t;
        if (role == 0) {
            out[b * 14 + i] = qn[i];
        } else {
            float dv = dq0[i] + (h / 6.0f) * dqs[i];
            dv = fminf(fmaxf(dv, -MAX_VEL), MAX_VEL);
            out[b * 14 + DOF + i] = dv;
        }
    }

    // ---- FK: row `role` of T propagates independently; ee component = role ----
    float TRr[3] = { role == 0 ? 1.f : 0.f, role == 0 ? 0.f : 1.f, 0.f };
    float Tpr = 0.f;
#pragma unroll
    for (int i = 0; i < DOF; i++) {
        float s, c;
        __sincosf(qn[i], &s, &c);
        const float* w = sp.w[i];
        const float* v = sp.v[i];
        float omc = 1.0f - c;
        float Re[9];
        Re[0] = c + omc * w[0] * w[0];
        Re[1] = s * (-w[2]) + omc * w[0] * w[1];
        Re[2] = s * ( w[1]) + omc * w[0] * w[2];
        Re[3] = s * ( w[2]) + omc * w[1] * w[0];
        Re[4] = c + omc * w[1] * w[1];
        Re[5] = s * (-w[0]) + omc * w[1] * w[2];
        Re[6] = s * (-w[1]) + omc * w[2] * w[0];
        Re[7] = s * ( w[0]) + omc * w[2] * w[1];
        Re[8] = c + omc * w[2] * w[2];
        float th = qn[i];
        float tms = th - s;
        float pe[3];
#pragma unroll
        for (int k = 0; k < 3; k++)
            pe[k] = th * v[k] + omc * sp.wxv[i][k] + tms * (w[k] * sp.wdv[i] - v[k]);
        const float* Mr = sp.Mr[i];
        const float* Mp = sp.Mp[i];
        float Tm[3];
#pragma unroll
        for (int cc2 = 0; cc2 < 3; cc2++)
            Tm[cc2] = TRr[0] * Mr[0 * 3 + cc2] + TRr[1] * Mr[1 * 3 + cc2] + TRr[2] * Mr[2 * 3 + cc2];
        Tpr += TRr[0] * Mp[0] + TRr[1] * Mp[1] + TRr[2] * Mp[2]
             + Tm[0] * pe[0] + Tm[1] * pe[1] + Tm[2] * pe[2];
        float nTR[3];
#pragma unroll
        for (int cc2 = 0; cc2 < 3; cc2++)
            nTR[cc2] = Tm[0] * Re[0 * 3 + cc2] + Tm[1] * Re[1 * 3 + cc2] + Tm[2] * Re[2 * 3 + cc2];
        TRr[0] = nTR[0]; TRr[1] = nTR[1]; TRr[2] = nTR[2];
    }
    const float* Mp7 = sp.Mp[DOF];
    float e = TRr[0] * Mp7[0] + TRr[1] * Mp7[1] + TRr[2] * Mp7[2] + Tpr;
    out[BATCH * 14 + b * 2 + role] = e;
}

extern "C" void kernel_launch(void* const* d_in, const int* in_sizes, int n_in,
                              void* d_out, int out_size) {
    const float* state   = (const float*)d_in[0];
    const float* action  = (const float*)d_in[1];
    const float* M_      = (const float*)d_in[2];
    const float* A_      = (const float*)d_in[3];
    const float* G_      = (const float*)d_in[4];
    const float* gravity = (const float*)d_in[5];
    float* out = (float*)d_out;

    arm_kernel<<<BATCH / 32, NTHREADS>>>(state, action, M_, A_, G_, gravity, out);
}